// round 1
// baseline (speedup 1.0000x reference)
#include <cuda_runtime.h>
#include <cuda_bf16.h>
#include <math.h>

// Problem constants
#define TOK_L   4096          // H*W per batch
#define NBATCH  2
#define NTOK    8192          // B * L
#define CDIM    256
#define DI      512
#define NSTATE  16
#define RRANK   32

// ------------------------- scratch (device globals; no allocation) ---------
__device__ float g_encp [NTOK * DI];
__device__ float g_comb [NTOK * DI];
__device__ float g_gate [NTOK * DI];
__device__ float g_xm   [NTOK * DI];
__device__ float g_z    [NTOK * DI];
__device__ float g_u    [NTOK * DI];
__device__ float g_xdbl [NTOK * 64];
__device__ float g_dt   [NTOK * DI];
__device__ float g_y    [NTOK * DI];
__device__ float g_gated[NTOK * DI];
__device__ float g_res  [NTOK * CDIM];

// ------------------------- helpers -----------------------------------------
__device__ __forceinline__ float sigmoidf_(float x) { return 1.f / (1.f + __expf(-x)); }

// ------------------------- epilogue functors -------------------------------
struct EpiEnc {               // enc_p = enc @ enc_w + enc_b
    const float* b;
    __device__ void operator()(int t, int j, float a) const {
        g_encp[(size_t)t * DI + j] = a + b[j];
    }
};
struct EpiDec {               // dec_proj; combined + raw gate
    const float* b;
    __device__ void operator()(int t, int j, float a) const {
        float v = a + b[j];
        if (j < DI) {
            float e = g_encp[(size_t)t * DI + j];
            g_comb[(size_t)t * DI + j] = v * sigmoidf_(e) + e;
        } else {
            g_gate[(size_t)t * DI + (j - DI)] = v;
        }
    }
};
struct EpiXZ {                // xz split into xm / z
    const float* b;
    __device__ void operator()(int t, int j, float a) const {
        float v = a + b[j];
        if (j < DI) g_xm[(size_t)t * DI + j] = v;
        else        g_z [(size_t)t * DI + (j - DI)] = v;
    }
};
struct EpiXdbl {              // x_dbl (no bias)
    __device__ void operator()(int t, int j, float a) const {
        g_xdbl[(size_t)t * 64 + j] = a;
    }
};
struct EpiDt {                // dt = softplus(. + dt_b)
    const float* b;
    __device__ void operator()(int t, int j, float a) const {
        float x = a + b[j];
        float sp = (x > 20.f) ? x : log1pf(expf(x));
        g_dt[(size_t)t * DI + j] = sp;
    }
};
struct EpiMout {              // processed * sigmoid(dec_gate)
    const float* b;
    __device__ void operator()(int t, int j, float a) const {
        float v = a + b[j];
        float g = g_gate[(size_t)t * DI + j];
        g_gated[(size_t)t * DI + j] = v * sigmoidf_(g);
    }
};
struct EpiOut {               // out + dec residual
    const float* b; const float* dec;
    __device__ void operator()(int t, int j, float a) const {
        int bt = t >> 12, l = t & (TOK_L - 1);
        float d = dec[((size_t)bt * CDIM + j) * TOK_L + l];
        g_res[(size_t)t * CDIM + j] = a + b[j] + d;
    }
};

// ------------------------- tiled fp32 GEMM ---------------------------------
// C[t, j] = sum_k A[t, k] * W[k, j]    (W row-major, ld = N)
// ACOL=true : A is (B, K, L) channel-major (NCHW features), addr = b*K*L + k*L + l
// ACOL=false: A row-major with leading dim `lda`
template <bool ACOL, class Epi>
__global__ __launch_bounds__(256) void gemm_k(
    const float* __restrict__ A, const float* __restrict__ W,
    int K, int N, int lda, Epi epi)
{
    const int BM = 128, BN = 64, BK = 16;
    __shared__ float As[BK][BM + 2];
    __shared__ float Ws[BK][BN];

    int tid = threadIdx.x;
    int tx = tid & 15;   // n sub-index
    int ty = tid >> 4;   // m sub-index
    int t0 = blockIdx.y * BM;
    int n0 = blockIdx.x * BN;

    const float* Abase;
    if (ACOL) {
        int bt = t0 >> 12;
        int l0 = t0 & (TOK_L - 1);
        Abase = A + (size_t)bt * K * TOK_L + l0;
    } else {
        Abase = A + (size_t)t0 * lda;
    }

    float acc[8][4];
#pragma unroll
    for (int i = 0; i < 8; i++)
#pragma unroll
        for (int j = 0; j < 4; j++) acc[i][j] = 0.f;

    for (int k0 = 0; k0 < K; k0 += BK) {
        if (ACOL) {
#pragma unroll
            for (int r = 0; r < 8; r++) {
                int idx = tid + 256 * r;
                int kk = idx >> 7, m = idx & 127;
                As[kk][m] = Abase[(size_t)(k0 + kk) * TOK_L + m];
            }
        } else {
#pragma unroll
            for (int r = 0; r < 8; r++) {
                int idx = tid + 256 * r;
                int kk = idx & 15, m = idx >> 4;
                As[kk][m] = Abase[(size_t)m * lda + k0 + kk];
            }
        }
        {
            int kk = tid >> 4;
            int c  = (tid & 15) * 4;
            float4 v = *reinterpret_cast<const float4*>(&W[(size_t)(k0 + kk) * N + n0 + c]);
            Ws[kk][c] = v.x; Ws[kk][c + 1] = v.y; Ws[kk][c + 2] = v.z; Ws[kk][c + 3] = v.w;
        }
        __syncthreads();
#pragma unroll
        for (int kk = 0; kk < BK; kk++) {
            float ra[8], rw[4];
#pragma unroll
            for (int i = 0; i < 8; i++) ra[i] = As[kk][ty + 16 * i];
#pragma unroll
            for (int j = 0; j < 4; j++) rw[j] = Ws[kk][tx + 16 * j];
#pragma unroll
            for (int i = 0; i < 8; i++)
#pragma unroll
                for (int j = 0; j < 4; j++) acc[i][j] = fmaf(ra[i], rw[j], acc[i][j]);
        }
        __syncthreads();
    }

#pragma unroll
    for (int i = 0; i < 8; i++) {
        int t = t0 + ty + 16 * i;
#pragma unroll
        for (int j = 0; j < 4; j++) {
            epi(t, n0 + tx + 16 * j, acc[i][j]);
        }
    }
}

// ------------------------- depthwise causal conv (K=4) + SiLU --------------
__global__ __launch_bounds__(256) void conv_silu_k(
    const float* __restrict__ w, const float* __restrict__ bias)
{
    int t = blockIdx.x;                       // global token 0..8191
    int d = blockIdx.y * 256 + threadIdx.x;   // channel
    int l = t & (TOK_L - 1);
    float acc = bias[d];
#pragma unroll
    for (int k = 0; k < 4; k++) {
        int li = l - 3 + k;
        if (li >= 0) acc = fmaf(g_xm[(size_t)(t - 3 + k) * DI + d], w[d * 4 + k], acc);
    }
    g_u[(size_t)t * DI + d] = acc * sigmoidf_(acc);
}

// ------------------------- selective scan (16 lanes = 16 states) -----------
__global__ __launch_bounds__(256) void scan_k(
    const float* __restrict__ A_log, const float* __restrict__ Dp)
{
    int tid  = threadIdx.x;
    int gid  = blockIdx.x * (blockDim.x >> 4) + (tid >> 4); // (b,d) pair, 0..1023
    int lane = tid & 15;
    int b = gid >> 9;
    int d = gid & (DI - 1);

    float a  = -__expf(A_log[d * NSTATE + lane]);
    float Dv = Dp[d];
    float h  = 0.f;
    size_t base = (size_t)b * TOK_L;

    for (int l = 0; l < TOK_L; l++) {
        size_t tt = base + l;
        float dtv = g_dt[tt * DI + d];
        float uv  = g_u [tt * DI + d];
        float Bv  = g_xdbl[tt * 64 + RRANK + lane];
        float Cv  = g_xdbl[tt * 64 + RRANK + NSTATE + lane];
        h = fmaf(h, __expf(dtv * a), (dtv * uv) * Bv);
        float s = h * Cv;
        s += __shfl_xor_sync(0xffffffffu, s, 1);
        s += __shfl_xor_sync(0xffffffffu, s, 2);
        s += __shfl_xor_sync(0xffffffffu, s, 4);
        s += __shfl_xor_sync(0xffffffffu, s, 8);
        if (lane == 0) {
            float zv = g_z[tt * DI + d];
            g_y[tt * DI + d] = (s + uv * Dv) * (zv * sigmoidf_(zv));
        }
    }
}

// ------------------------- LayerNorm + NCHW output -------------------------
__global__ __launch_bounds__(256) void ln_k(
    const float* __restrict__ g, const float* __restrict__ be,
    float* __restrict__ out)
{
    __shared__ float sm[32][257];
    int tid = threadIdx.x;
    int warp = tid >> 5, lane = tid & 31;
    int t0 = blockIdx.x * 32;

    for (int i = 0; i < 4; i++) {
        int tl = warp * 4 + i;
        int t  = t0 + tl;
        const float* row = g_res + (size_t)t * CDIM;
        float v[8];
        float s = 0.f, sq = 0.f;
#pragma unroll
        for (int r = 0; r < 2; r++) {
            float4 p = reinterpret_cast<const float4*>(row)[lane * 2 + r];
            v[r * 4] = p.x; v[r * 4 + 1] = p.y; v[r * 4 + 2] = p.z; v[r * 4 + 3] = p.w;
        }
#pragma unroll
        for (int k = 0; k < 8; k++) { s += v[k]; sq += v[k] * v[k]; }
#pragma unroll
        for (int o = 16; o; o >>= 1) {
            s  += __shfl_xor_sync(0xffffffffu, s,  o);
            sq += __shfl_xor_sync(0xffffffffu, sq, o);
        }
        float mu  = s * (1.f / CDIM);
        float var = sq * (1.f / CDIM) - mu * mu;
        float inv = rsqrtf(var + 1e-5f);
#pragma unroll
        for (int k = 0; k < 8; k++) {
            int c = lane * 8 + k;
            sm[tl][c] = (v[k] - mu) * inv * g[c] + be[c];
        }
    }
    __syncthreads();

    int bt = t0 >> 12;
    int l0 = t0 & (TOK_L - 1);
#pragma unroll 4
    for (int r = 0; r < 32; r++) {
        int idx = tid + 256 * r;
        int l = idx & 31;
        int c = idx >> 5;
        out[((size_t)bt * CDIM + c) * TOK_L + l0 + l] = sm[l][c];
    }
}

// ------------------------- launch ------------------------------------------
extern "C" void kernel_launch(void* const* d_in, const int* in_sizes, int n_in,
                              void* d_out, int out_size)
{
    const float* decoder  = (const float*)d_in[0];
    const float* encoder  = (const float*)d_in[1];
    const float* dec_w    = (const float*)d_in[2];
    const float* dec_b    = (const float*)d_in[3];
    const float* enc_w    = (const float*)d_in[4];
    const float* enc_b    = (const float*)d_in[5];
    const float* out_w    = (const float*)d_in[6];
    const float* out_b    = (const float*)d_in[7];
    const float* ln_g     = (const float*)d_in[8];
    const float* ln_b     = (const float*)d_in[9];
    const float* in_w     = (const float*)d_in[10];
    const float* in_b     = (const float*)d_in[11];
    const float* conv_w   = (const float*)d_in[12];
    const float* conv_b   = (const float*)d_in[13];
    const float* x_proj_w = (const float*)d_in[14];
    const float* dt_w     = (const float*)d_in[15];
    const float* dt_b     = (const float*)d_in[16];
    const float* A_log    = (const float*)d_in[17];
    const float* D_param  = (const float*)d_in[18];
    const float* m_out_w  = (const float*)d_in[19];
    const float* m_out_b  = (const float*)d_in[20];
    float* out = (float*)d_out;

    void* pxm; cudaGetSymbolAddress(&pxm, g_xm);        // unused directly; scratch via globals

    dim3 blk(256);
    const int MB = NTOK / 128;                          // 64 M-tiles

    // 1. enc_p = enc @ enc_w + enc_b               (K=256, N=512, A NCHW)
    gemm_k<true,  EpiEnc ><<<dim3(DI / 64, MB), blk>>>(encoder, enc_w, CDIM, DI, 0, EpiEnc{enc_b});
    // 2. dec_proj -> combined + gate               (K=256, N=1024, A NCHW)
    gemm_k<true,  EpiDec ><<<dim3(2 * DI / 64, MB), blk>>>(decoder, dec_w, CDIM, 2 * DI, 0, EpiDec{dec_b});
    // 3. xz = combined @ in_w -> xm, z             (K=512, N=1024)
    gemm_k<false, EpiXZ  ><<<dim3(2 * DI / 64, MB), blk>>>(g_comb, in_w, DI, 2 * DI, DI, EpiXZ{in_b});
    // 4. depthwise conv + SiLU -> u
    conv_silu_k<<<dim3(NTOK, DI / 256), blk>>>(conv_w, conv_b);
    // 5. x_dbl = u @ x_proj_w                      (K=512, N=64)
    gemm_k<false, EpiXdbl><<<dim3(1, MB), blk>>>(g_u, x_proj_w, DI, 64, DI, EpiXdbl{});
    // 6. dt = softplus(x_dbl[:, :32] @ dt_w + dt_b) (K=32, N=512, lda=64)
    gemm_k<false, EpiDt  ><<<dim3(DI / 64, MB), blk>>>(g_xdbl, dt_w, RRANK, DI, 64, EpiDt{dt_b});
    // 7. selective scan -> y = (scan + u*D) * silu(z)
    scan_k<<<64, blk>>>(A_log, D_param);
    // 8. processed = y @ m_out_w + b, * sigmoid(gate)  (K=512, N=512)
    gemm_k<false, EpiMout><<<dim3(DI / 64, MB), blk>>>(g_y, m_out_w, DI, DI, DI, EpiMout{m_out_b});
    // 9. out = gated @ out_w + out_b + dec         (K=512, N=256)
    gemm_k<false, EpiOut ><<<dim3(CDIM / 64, MB), blk>>>(g_gated, out_w, DI, CDIM, DI, EpiOut{out_b, decoder});
    // 10. LayerNorm + transpose to NCHW
    ln_k<<<NTOK / 32, blk>>>(ln_g, ln_b, out);
}

// round 2
// speedup vs baseline: 2.2334x; 2.2334x over previous
#include <cuda_runtime.h>
#include <cuda_bf16.h>
#include <math.h>

// Problem constants
#define TOK_L   4096          // H*W per batch
#define NBATCH  2
#define NTOK    8192          // B * L
#define CDIM    256
#define DI      512
#define NSTATE  16
#define RRANK   32
#define CHUNK   128
#define NCHUNK  32            // TOK_L / CHUNK

// ------------------------- scratch (device globals; no allocation) ---------
__device__ float g_encp [NTOK * DI];
__device__ float g_comb [NTOK * DI];
__device__ float g_gate [NTOK * DI];
__device__ float g_xm   [NTOK * DI];
__device__ float g_z    [NTOK * DI];
__device__ float g_u    [NTOK * DI];
__device__ float g_xdbl [NTOK * 64];
__device__ float g_dt   [NTOK * DI];
__device__ float g_y    [NTOK * DI];
__device__ float g_gated[NTOK * DI];
__device__ float g_res  [NTOK * CDIM];
__device__ float g_hend  [NBATCH * NCHUNK * DI * NSTATE];
__device__ float g_Pend  [NBATCH * NCHUNK * DI * NSTATE];
__device__ float g_hstart[NBATCH * NCHUNK * DI * NSTATE];

// ------------------------- helpers -----------------------------------------
__device__ __forceinline__ float sigmoidf_(float x) { return 1.f / (1.f + __expf(-x)); }

// ------------------------- epilogue functors -------------------------------
struct EpiEnc {
    const float* b;
    __device__ void operator()(int t, int j, float a) const {
        g_encp[(size_t)t * DI + j] = a + b[j];
    }
};
struct EpiDec {
    const float* b;
    __device__ void operator()(int t, int j, float a) const {
        float v = a + b[j];
        if (j < DI) {
            float e = g_encp[(size_t)t * DI + j];
            g_comb[(size_t)t * DI + j] = v * sigmoidf_(e) + e;
        } else {
            g_gate[(size_t)t * DI + (j - DI)] = v;
        }
    }
};
struct EpiXZ {
    const float* b;
    __device__ void operator()(int t, int j, float a) const {
        float v = a + b[j];
        if (j < DI) g_xm[(size_t)t * DI + j] = v;
        else        g_z [(size_t)t * DI + (j - DI)] = v;
    }
};
struct EpiXdbl {
    __device__ void operator()(int t, int j, float a) const {
        g_xdbl[(size_t)t * 64 + j] = a;
    }
};
struct EpiDt {
    const float* b;
    __device__ void operator()(int t, int j, float a) const {
        float x = a + b[j];
        float sp = (x > 20.f) ? x : log1pf(expf(x));
        g_dt[(size_t)t * DI + j] = sp;
    }
};
struct EpiMout {
    const float* b;
    __device__ void operator()(int t, int j, float a) const {
        float v = a + b[j];
        float g = g_gate[(size_t)t * DI + j];
        g_gated[(size_t)t * DI + j] = v * sigmoidf_(g);
    }
};
struct EpiOut {
    const float* b; const float* dec;
    __device__ void operator()(int t, int j, float a) const {
        int bt = t >> 12, l = t & (TOK_L - 1);
        float d = dec[((size_t)bt * CDIM + j) * TOK_L + l];
        g_res[(size_t)t * CDIM + j] = a + b[j] + d;
    }
};

// ------------------------- big double-buffered fp32 GEMM (128x128x16) ------
// C[t, j] = sum_k A[t, k] * W[k, j]    (W row-major, ld = N; N % 128 == 0)
// ACOL=true : A is (B, K, L) channel-major, addr = b*K*L + k*L + l
template <bool ACOL, class Epi>
__global__ __launch_bounds__(256) void gemm128(
    const float* __restrict__ A, const float* __restrict__ W,
    int K, int N, int lda, Epi epi)
{
    const int BM = 128, BN = 128, BK = 16;
    __shared__ float As[2][BK][BM + 4];
    __shared__ float Ws[2][BK][BN];

    int tid = threadIdx.x;
    int tx = tid & 15;    // n group
    int ty = tid >> 4;    // m group
    int t0 = blockIdx.y * BM;
    int n0 = blockIdx.x * BN;

    const float* Abase;
    if (ACOL) {
        int bt = t0 >> 12;
        int l0 = t0 & (TOK_L - 1);
        Abase = A + (size_t)bt * K * TOK_L + l0;
    } else {
        Abase = A + (size_t)t0 * lda;
    }

    float4 avec[2], wvec[2];

    auto ldTile = [&](int k0) {
#pragma unroll
        for (int r = 0; r < 2; r++) {
            int e = tid + 256 * r;
            if (ACOL) {
                int kk = e >> 5, m4 = e & 31;
                avec[r] = *reinterpret_cast<const float4*>(
                    &Abase[(size_t)(k0 + kk) * TOK_L + m4 * 4]);
            } else {
                int m = e >> 2, kc = e & 3;
                avec[r] = *reinterpret_cast<const float4*>(
                    &Abase[(size_t)m * lda + k0 + kc * 4]);
            }
            int kk = e >> 5, c4 = e & 31;
            wvec[r] = *reinterpret_cast<const float4*>(
                &W[(size_t)(k0 + kk) * N + n0 + c4 * 4]);
        }
    };
    auto stTile = [&](int buf) {
#pragma unroll
        for (int r = 0; r < 2; r++) {
            int e = tid + 256 * r;
            if (ACOL) {
                int kk = e >> 5, m4 = e & 31;
                *reinterpret_cast<float4*>(&As[buf][kk][m4 * 4]) = avec[r];
            } else {
                int m = e >> 2, kc = e & 3;
                As[buf][kc * 4 + 0][m] = avec[r].x;
                As[buf][kc * 4 + 1][m] = avec[r].y;
                As[buf][kc * 4 + 2][m] = avec[r].z;
                As[buf][kc * 4 + 3][m] = avec[r].w;
            }
            int kk = e >> 5, c4 = e & 31;
            *reinterpret_cast<float4*>(&Ws[buf][kk][c4 * 4]) = wvec[r];
        }
    };

    float acc[8][8];
#pragma unroll
    for (int i = 0; i < 8; i++)
#pragma unroll
        for (int j = 0; j < 8; j++) acc[i][j] = 0.f;

    ldTile(0);
    stTile(0);
    __syncthreads();

    int nk = K / BK;
    for (int kt = 0; kt < nk; kt++) {
        int buf = kt & 1;
        if (kt + 1 < nk) ldTile((kt + 1) * BK);
#pragma unroll
        for (int kk = 0; kk < BK; kk++) {
            float ra[8], rw[8];
            *reinterpret_cast<float4*>(&ra[0]) = *reinterpret_cast<const float4*>(&As[buf][kk][ty * 8]);
            *reinterpret_cast<float4*>(&ra[4]) = *reinterpret_cast<const float4*>(&As[buf][kk][ty * 8 + 4]);
            *reinterpret_cast<float4*>(&rw[0]) = *reinterpret_cast<const float4*>(&Ws[buf][kk][tx * 8]);
            *reinterpret_cast<float4*>(&rw[4]) = *reinterpret_cast<const float4*>(&Ws[buf][kk][tx * 8 + 4]);
#pragma unroll
            for (int i = 0; i < 8; i++)
#pragma unroll
                for (int j = 0; j < 8; j++) acc[i][j] = fmaf(ra[i], rw[j], acc[i][j]);
        }
        if (kt + 1 < nk) {
            stTile(buf ^ 1);
            __syncthreads();
        }
    }

#pragma unroll
    for (int i = 0; i < 8; i++) {
        int t = t0 + ty * 8 + i;
#pragma unroll
        for (int j = 0; j < 8; j++) {
            epi(t, n0 + tx * 8 + j, acc[i][j]);
        }
    }
}

// ------------------------- small GEMM (128x64) for N=64 case ---------------
template <class Epi>
__global__ __launch_bounds__(256) void gemm_small(
    const float* __restrict__ A, const float* __restrict__ W,
    int K, int N, int lda, Epi epi)
{
    const int BM = 128, BN = 64, BK = 16;
    __shared__ float As[BK][BM + 2];
    __shared__ float Ws[BK][BN];

    int tid = threadIdx.x;
    int tx = tid & 15;
    int ty = tid >> 4;
    int t0 = blockIdx.y * BM;
    int n0 = blockIdx.x * BN;
    const float* Abase = A + (size_t)t0 * lda;

    float acc[8][4];
#pragma unroll
    for (int i = 0; i < 8; i++)
#pragma unroll
        for (int j = 0; j < 4; j++) acc[i][j] = 0.f;

    for (int k0 = 0; k0 < K; k0 += BK) {
#pragma unroll
        for (int r = 0; r < 8; r++) {
            int idx = tid + 256 * r;
            int kk = idx & 15, m = idx >> 4;
            As[kk][m] = Abase[(size_t)m * lda + k0 + kk];
        }
        {
            int kk = tid >> 4;
            int c  = (tid & 15) * 4;
            float4 v = *reinterpret_cast<const float4*>(&W[(size_t)(k0 + kk) * N + n0 + c]);
            Ws[kk][c] = v.x; Ws[kk][c + 1] = v.y; Ws[kk][c + 2] = v.z; Ws[kk][c + 3] = v.w;
        }
        __syncthreads();
#pragma unroll
        for (int kk = 0; kk < BK; kk++) {
            float ra[8], rw[4];
#pragma unroll
            for (int i = 0; i < 8; i++) ra[i] = As[kk][ty + 16 * i];
#pragma unroll
            for (int j = 0; j < 4; j++) rw[j] = Ws[kk][tx + 16 * j];
#pragma unroll
            for (int i = 0; i < 8; i++)
#pragma unroll
                for (int j = 0; j < 4; j++) acc[i][j] = fmaf(ra[i], rw[j], acc[i][j]);
        }
        __syncthreads();
    }

#pragma unroll
    for (int i = 0; i < 8; i++) {
        int t = t0 + ty + 16 * i;
#pragma unroll
        for (int j = 0; j < 4; j++) epi(t, n0 + tx + 16 * j, acc[i][j]);
    }
}

// ------------------------- depthwise causal conv (K=4) + SiLU --------------
__global__ __launch_bounds__(256) void conv_silu_k(
    const float* __restrict__ w, const float* __restrict__ bias)
{
    int t = blockIdx.x;
    int d = blockIdx.y * 256 + threadIdx.x;
    int l = t & (TOK_L - 1);
    float acc = bias[d];
#pragma unroll
    for (int k = 0; k < 4; k++) {
        int li = l - 3 + k;
        if (li >= 0) acc = fmaf(g_xm[(size_t)(t - 3 + k) * DI + d], w[d * 4 + k], acc);
    }
    g_u[(size_t)t * DI + d] = acc * sigmoidf_(acc);
}

// ------------------------- chunked selective scan ---------------------------
// pass 1: per-chunk local scan (h0=0) -> chunk end state + decay product
__global__ __launch_bounds__(256) void scan_pass1(const float* __restrict__ A_log)
{
    int tid  = threadIdx.x;
    int g    = blockIdx.x * 16 + (tid >> 4);   // 0 .. 32767
    int lane = tid & 15;
    int d = g & (DI - 1);
    int c = (g >> 9) & (NCHUNK - 1);
    int b = g >> 14;

    float a = -__expf(A_log[d * NSTATE + lane]);
    float h = 0.f, p = 1.f;
    size_t base = (size_t)b * TOK_L + (size_t)c * CHUNK;

    for (int l = 0; l < CHUNK; l++) {
        size_t tt = base + l;
        float dtv = g_dt[tt * DI + d];
        float uv  = g_u [tt * DI + d];
        float Bv  = g_xdbl[tt * 64 + RRANK + lane];
        float dA  = __expf(dtv * a);
        h = fmaf(h, dA, (dtv * uv) * Bv);
        p *= dA;
    }
    size_t idx = (((size_t)b * NCHUNK + c) * DI + d) * NSTATE + lane;
    g_hend[idx] = h;
    g_Pend[idx] = p;
}

// pass 2: stitch chunk boundaries (32 serial steps per lane)
__global__ __launch_bounds__(256) void scan_pass2()
{
    int tid = blockIdx.x * 256 + threadIdx.x;   // 0 .. 16383
    int b  = tid >> 13;
    int dn = tid & 8191;
    float h = 0.f;
    for (int c = 0; c < NCHUNK; c++) {
        size_t idx = ((size_t)(b * NCHUNK + c)) * 8192 + dn;
        g_hstart[idx] = h;
        h = g_hend[idx] + g_Pend[idx] * h;
    }
}

// pass 3: rescan chunk from true start state, emit y
__global__ __launch_bounds__(256) void scan_pass3(
    const float* __restrict__ A_log, const float* __restrict__ Dp)
{
    int tid  = threadIdx.x;
    int g    = blockIdx.x * 16 + (tid >> 4);
    int lane = tid & 15;
    int d = g & (DI - 1);
    int c = (g >> 9) & (NCHUNK - 1);
    int b = g >> 14;

    float a  = -__expf(A_log[d * NSTATE + lane]);
    float Dv = Dp[d];
    size_t sidx = (((size_t)b * NCHUNK + c) * DI + d) * NSTATE + lane;
    float h = g_hstart[sidx];
    size_t base = (size_t)b * TOK_L + (size_t)c * CHUNK;

    for (int l = 0; l < CHUNK; l++) {
        size_t tt = base + l;
        float dtv = g_dt[tt * DI + d];
        float uv  = g_u [tt * DI + d];
        float Bv  = g_xdbl[tt * 64 + RRANK + lane];
        float Cv  = g_xdbl[tt * 64 + RRANK + NSTATE + lane];
        float dA  = __expf(dtv * a);
        h = fmaf(h, dA, (dtv * uv) * Bv);
        float s = h * Cv;
        s += __shfl_xor_sync(0xffffffffu, s, 1);
        s += __shfl_xor_sync(0xffffffffu, s, 2);
        s += __shfl_xor_sync(0xffffffffu, s, 4);
        s += __shfl_xor_sync(0xffffffffu, s, 8);
        if (lane == 0) {
            float zv = g_z[tt * DI + d];
            g_y[tt * DI + d] = (s + uv * Dv) * (zv * sigmoidf_(zv));
        }
    }
}

// ------------------------- LayerNorm + NCHW output -------------------------
__global__ __launch_bounds__(256) void ln_k(
    const float* __restrict__ g, const float* __restrict__ be,
    float* __restrict__ out)
{
    __shared__ float sm[32][257];
    int tid = threadIdx.x;
    int warp = tid >> 5, lane = tid & 31;
    int t0 = blockIdx.x * 32;

    for (int i = 0; i < 4; i++) {
        int tl = warp * 4 + i;
        int t  = t0 + tl;
        const float* row = g_res + (size_t)t * CDIM;
        float v[8];
        float s = 0.f, sq = 0.f;
#pragma unroll
        for (int r = 0; r < 2; r++) {
            float4 p = reinterpret_cast<const float4*>(row)[lane * 2 + r];
            v[r * 4] = p.x; v[r * 4 + 1] = p.y; v[r * 4 + 2] = p.z; v[r * 4 + 3] = p.w;
        }
#pragma unroll
        for (int k = 0; k < 8; k++) { s += v[k]; sq += v[k] * v[k]; }
#pragma unroll
        for (int o = 16; o; o >>= 1) {
            s  += __shfl_xor_sync(0xffffffffu, s,  o);
            sq += __shfl_xor_sync(0xffffffffu, sq, o);
        }
        float mu  = s * (1.f / CDIM);
        float var = sq * (1.f / CDIM) - mu * mu;
        float inv = rsqrtf(var + 1e-5f);
#pragma unroll
        for (int k = 0; k < 8; k++) {
            int c = lane * 8 + k;
            sm[tl][c] = (v[k] - mu) * inv * g[c] + be[c];
        }
    }
    __syncthreads();

    int bt = t0 >> 12;
    int l0 = t0 & (TOK_L - 1);
#pragma unroll 4
    for (int r = 0; r < 32; r++) {
        int idx = tid + 256 * r;
        int l = idx & 31;
        int c = idx >> 5;
        out[((size_t)bt * CDIM + c) * TOK_L + l0 + l] = sm[l][c];
    }
}

// ------------------------- launch ------------------------------------------
extern "C" void kernel_launch(void* const* d_in, const int* in_sizes, int n_in,
                              void* d_out, int out_size)
{
    const float* decoder  = (const float*)d_in[0];
    const float* encoder  = (const float*)d_in[1];
    const float* dec_w    = (const float*)d_in[2];
    const float* dec_b    = (const float*)d_in[3];
    const float* enc_w    = (const float*)d_in[4];
    const float* enc_b    = (const float*)d_in[5];
    const float* out_w    = (const float*)d_in[6];
    const float* out_b    = (const float*)d_in[7];
    const float* ln_g     = (const float*)d_in[8];
    const float* ln_b     = (const float*)d_in[9];
    const float* in_w     = (const float*)d_in[10];
    const float* in_b     = (const float*)d_in[11];
    const float* conv_w   = (const float*)d_in[12];
    const float* conv_b   = (const float*)d_in[13];
    const float* x_proj_w = (const float*)d_in[14];
    const float* dt_w     = (const float*)d_in[15];
    const float* dt_b     = (const float*)d_in[16];
    const float* A_log    = (const float*)d_in[17];
    const float* D_param  = (const float*)d_in[18];
    const float* m_out_w  = (const float*)d_in[19];
    const float* m_out_b  = (const float*)d_in[20];
    float* out = (float*)d_out;

    dim3 blk(256);
    const int MB = NTOK / 128;   // 64 M-tiles

    // 1. enc_p = enc @ enc_w + enc_b               (K=256, N=512, A NCHW)
    gemm128<true,  EpiEnc ><<<dim3(DI / 128, MB), blk>>>(encoder, enc_w, CDIM, DI, 0, EpiEnc{enc_b});
    // 2. dec_proj -> combined + gate               (K=256, N=1024, A NCHW)
    gemm128<true,  EpiDec ><<<dim3(2 * DI / 128, MB), blk>>>(decoder, dec_w, CDIM, 2 * DI, 0, EpiDec{dec_b});
    // 3. xz = combined @ in_w -> xm, z             (K=512, N=1024)
    gemm128<false, EpiXZ  ><<<dim3(2 * DI / 128, MB), blk>>>(g_comb, in_w, DI, 2 * DI, DI, EpiXZ{in_b});
    // 4. depthwise conv + SiLU -> u
    conv_silu_k<<<dim3(NTOK, DI / 256), blk>>>(conv_w, conv_b);
    // 5. x_dbl = u @ x_proj_w                      (K=512, N=64)
    gemm_small<EpiXdbl><<<dim3(1, MB), blk>>>(g_u, x_proj_w, DI, 64, DI, EpiXdbl{});
    // 6. dt = softplus(x_dbl[:, :32] @ dt_w + dt_b) (K=32, N=512, lda=64)
    gemm128<false, EpiDt  ><<<dim3(DI / 128, MB), blk>>>(g_xdbl, dt_w, RRANK, DI, 64, EpiDt{dt_b});
    // 7-9. chunked selective scan
    scan_pass1<<<NBATCH * NCHUNK * DI / 16, blk>>>(A_log);
    scan_pass2<<<NBATCH * DI * NSTATE / 256, blk>>>();
    scan_pass3<<<NBATCH * NCHUNK * DI / 16, blk>>>(A_log, D_param);
    // 10. processed = y @ m_out_w + b, * sigmoid(gate)  (K=512, N=512)
    gemm128<false, EpiMout><<<dim3(DI / 128, MB), blk>>>(g_y, m_out_w, DI, DI, DI, EpiMout{m_out_b});
    // 11. out = gated @ out_w + out_b + dec        (K=512, N=256)
    gemm128<false, EpiOut ><<<dim3(CDIM / 128, MB), blk>>>(g_gated, out_w, DI, CDIM, DI, EpiOut{out_b, decoder});
    // 12. LayerNorm + transpose to NCHW
    ln_k<<<NTOK / 32, blk>>>(ln_g, ln_b, out);
}

// round 3
// speedup vs baseline: 8.0987x; 3.6261x over previous
#include <cuda_runtime.h>
#include <cuda_bf16.h>
#include <math.h>
#include <stdint.h>

// Problem constants
#define TOK_L   4096
#define NBATCH  2
#define NTOK    8192
#define CDIM    256
#define DI      512
#define NSTATE  16
#define RRANK   32
#define CHUNK   128
#define NCHUNK  32

// ------------------------- scratch (device globals) -------------------------
__device__ float g_encp [NTOK * DI];
__device__ float g_gate [NTOK * DI];
__device__ float g_xm   [NTOK * DI];
__device__ float g_z    [NTOK * DI];
__device__ float g_u    [NTOK * DI];
__device__ float g_xdbl [NTOK * 64];
__device__ float g_dt   [NTOK * DI];
__device__ float g_res  [NTOK * CDIM];
__device__ float g_hend  [NBATCH * NCHUNK * DI * NSTATE];
__device__ float g_Pend  [NBATCH * NCHUNK * DI * NSTATE];
__device__ float g_hstart[NBATCH * NCHUNK * DI * NSTATE];

// bf16 scratch
__device__ __nv_bfloat16 g_decbf  [NTOK * CDIM];
__device__ __nv_bfloat16 g_encbf  [NTOK * CDIM];
__device__ __nv_bfloat16 g_combbf [NTOK * DI];
__device__ __nv_bfloat16 g_ybf    [NTOK * DI];
__device__ __nv_bfloat16 g_gatedbf[NTOK * DI];
// bf16 weights
__device__ __nv_bfloat16 g_wdec [CDIM * 2 * DI];
__device__ __nv_bfloat16 g_wenc [CDIM * DI];
__device__ __nv_bfloat16 g_win  [DI * 2 * DI];
__device__ __nv_bfloat16 g_wmout[DI * DI];
__device__ __nv_bfloat16 g_wout [DI * CDIM];

// ------------------------- helpers -----------------------------------------
__device__ __forceinline__ float sigmoidf_(float x) { return 1.f / (1.f + __expf(-x)); }

#define CP_ASYNC16(dst, src) \
    asm volatile("cp.async.cg.shared.global [%0], [%1], 16;\n" :: "r"(dst), "l"(src))
#define CP_COMMIT() asm volatile("cp.async.commit_group;\n" ::: "memory")
#define CP_WAIT1()  asm volatile("cp.async.wait_group 1;\n" ::: "memory")

#define LDSM_X4(r0,r1,r2,r3,addr) \
    asm volatile("ldmatrix.sync.aligned.m8n8.x4.shared.b16 {%0,%1,%2,%3}, [%4];" \
        : "=r"(r0),"=r"(r1),"=r"(r2),"=r"(r3) : "r"(addr))
#define LDSM_X4T(r0,r1,r2,r3,addr) \
    asm volatile("ldmatrix.sync.aligned.m8n8.x4.trans.shared.b16 {%0,%1,%2,%3}, [%4];" \
        : "=r"(r0),"=r"(r1),"=r"(r2),"=r"(r3) : "r"(addr))

#define MMA16816(d, a, b) \
    asm volatile("mma.sync.aligned.m16n8k16.row.col.f32.bf16.bf16.f32 " \
        "{%0,%1,%2,%3}, {%4,%5,%6,%7}, {%8,%9}, {%0,%1,%2,%3};" \
        : "+f"(d[0]),"+f"(d[1]),"+f"(d[2]),"+f"(d[3]) \
        : "r"(a[0]),"r"(a[1]),"r"(a[2]),"r"(a[3]), "r"(b[0]),"r"(b[1]))

// ------------------------- epilogue functors -------------------------------
struct EpiEnc {
    const float* b;
    __device__ void operator()(int t, int j, float a) const {
        g_encp[(size_t)t * DI + j] = a + b[j];
    }
};
struct EpiDec {
    const float* b;
    __device__ void operator()(int t, int j, float a) const {
        float v = a + b[j];
        if (j < DI) {
            float e = g_encp[(size_t)t * DI + j];
            g_combbf[(size_t)t * DI + j] = __float2bfloat16(v * sigmoidf_(e) + e);
        } else {
            g_gate[(size_t)t * DI + (j - DI)] = v;
        }
    }
};
struct EpiXZ {
    const float* b;
    __device__ void operator()(int t, int j, float a) const {
        float v = a + b[j];
        if (j < DI) g_xm[(size_t)t * DI + j] = v;
        else        g_z [(size_t)t * DI + (j - DI)] = v;
    }
};
struct EpiXdbl {
    __device__ void operator()(int t, int j, float a) const {
        g_xdbl[(size_t)t * 64 + j] = a;
    }
};
struct EpiDt {
    const float* b;
    __device__ void operator()(int t, int j, float a) const {
        float x = a + b[j];
        float sp = (x > 20.f) ? x : log1pf(expf(x));
        g_dt[(size_t)t * DI + j] = sp;
    }
};
struct EpiMout {
    const float* b;
    __device__ void operator()(int t, int j, float a) const {
        float v = a + b[j];
        float g = g_gate[(size_t)t * DI + j];
        g_gatedbf[(size_t)t * DI + j] = __float2bfloat16(v * sigmoidf_(g));
    }
};
struct EpiOut {
    const float* b; const float* dec;
    __device__ void operator()(int t, int j, float a) const {
        int bt = t >> 12, l = t & (TOK_L - 1);
        float d = dec[((size_t)bt * CDIM + j) * TOK_L + l];
        g_res[(size_t)t * CDIM + j] = a + b[j] + d;
    }
};

// ------------------------- bf16 tensor-core GEMM ---------------------------
// C[t, j] = sum_k A[t, k] * W[k, j]; A row-major (lda), W row-major (ld=N)
// BM=128 BN=128 BK=64, 3-stage cp.async pipeline, mma.m16n8k16 bf16.
template <class Epi>
__global__ __launch_bounds__(256) void gemm_bf(
    const __nv_bfloat16* __restrict__ A, const __nv_bfloat16* __restrict__ W,
    int K, int N, int lda, Epi epi)
{
    extern __shared__ char smem[];
    const int ASZ = 128 * 128;       // bytes per A stage (128 rows x 64 bf16)
    const int BSZ = 64 * 256;        // bytes per B stage (64 rows x 128 bf16)
    uint32_t sbase = (uint32_t)__cvta_generic_to_shared(smem);

    int tid = threadIdx.x;
    int w = tid >> 5, lane = tid & 31;
    int wm = w >> 2, wn = w & 3;     // 2 x 4 warp grid
    int t0 = blockIdx.y * 128, n0 = blockIdx.x * 128;

    const __nv_bfloat16* Ab = A + (size_t)t0 * lda;
    const __nv_bfloat16* Wb = W + n0;

    auto loadStage = [&](int s, int k0) {
        uint32_t as = sbase + s * (ASZ + BSZ);
        uint32_t bs = as + ASZ;
#pragma unroll
        for (int r = 0; r < 4; r++) {
            int idx = tid + 256 * r;
            int m = idx >> 3, kb = idx & 7;
            uint32_t off = m * 128 + ((kb ^ (m & 7)) << 4);
            CP_ASYNC16(as + off, Ab + (size_t)m * lda + k0 + kb * 8);
        }
#pragma unroll
        for (int r = 0; r < 4; r++) {
            int idx = tid + 256 * r;
            int k = idx >> 4, nb = idx & 15;
            uint32_t off = k * 256 + ((nb >> 3) << 7) + (((nb & 7) ^ (k & 7)) << 4);
            CP_ASYNC16(bs + off, Wb + (size_t)(k0 + k) * N + nb * 8);
        }
    };

    float acc[4][4][4];
#pragma unroll
    for (int i = 0; i < 4; i++)
#pragma unroll
        for (int j = 0; j < 4; j++)
#pragma unroll
            for (int c = 0; c < 4; c++) acc[i][j][c] = 0.f;

    int nk = K / 64;
    loadStage(0, 0);
    CP_COMMIT();
    if (nk > 1) loadStage(1, 64);
    CP_COMMIT();

    for (int kt = 0; kt < nk; kt++) {
        CP_WAIT1();
        __syncthreads();
        int s = kt % 3;
        if (kt + 2 < nk) loadStage((kt + 2) % 3, (kt + 2) * 64);
        CP_COMMIT();

        uint32_t as = sbase + s * (ASZ + BSZ);
        uint32_t bs = as + ASZ;
        int sub = lane >> 3;
#pragma unroll
        for (int ks = 0; ks < 4; ks++) {
            uint32_t afr[4][4];
            uint32_t bfr[4][2];
#pragma unroll
            for (int i = 0; i < 4; i++) {
                int row = wm * 64 + i * 16 + (lane & 7) + ((sub & 1) << 3);
                int kb = ks * 2 + (sub >> 1);
                uint32_t addr = as + row * 128 + ((kb ^ (row & 7)) << 4);
                LDSM_X4(afr[i][0], afr[i][1], afr[i][2], afr[i][3], addr);
            }
#pragma unroll
            for (int p = 0; p < 2; p++) {
                int k = ks * 16 + (lane & 7) + ((sub & 1) << 3);
                int nb = wn * 4 + p * 2 + (sub >> 1);
                uint32_t addr = bs + k * 256 + ((nb >> 3) << 7) + (((nb & 7) ^ (k & 7)) << 4);
                uint32_t r0, r1, r2, r3;
                LDSM_X4T(r0, r1, r2, r3, addr);
                bfr[p * 2][0] = r0;     bfr[p * 2][1] = r1;
                bfr[p * 2 + 1][0] = r2; bfr[p * 2 + 1][1] = r3;
            }
#pragma unroll
            for (int i = 0; i < 4; i++)
#pragma unroll
                for (int j = 0; j < 4; j++) MMA16816(acc[i][j], afr[i], bfr[j]);
        }
        __syncthreads();
    }

    int rbase = t0 + wm * 64 + (lane >> 2);
    int cbase = n0 + wn * 32 + (lane & 3) * 2;
#pragma unroll
    for (int i = 0; i < 4; i++)
#pragma unroll
        for (int j = 0; j < 4; j++) {
            epi(rbase + i * 16,     cbase + j * 8,     acc[i][j][0]);
            epi(rbase + i * 16,     cbase + j * 8 + 1, acc[i][j][1]);
            epi(rbase + i * 16 + 8, cbase + j * 8,     acc[i][j][2]);
            epi(rbase + i * 16 + 8, cbase + j * 8 + 1, acc[i][j][3]);
        }
}

// ------------------------- small fp32 GEMM (x_proj, dt) --------------------
template <class Epi>
__global__ __launch_bounds__(256) void gemm_small(
    const float* __restrict__ A, const float* __restrict__ W,
    int K, int N, int lda, Epi epi)
{
    const int BM = 128, BN = 64, BK = 16;
    __shared__ float As[BK][BM + 2];
    __shared__ float Ws[BK][BN];

    int tid = threadIdx.x;
    int tx = tid & 15;
    int ty = tid >> 4;
    int t0 = blockIdx.y * BM;
    int n0 = blockIdx.x * BN;
    const float* Abase = A + (size_t)t0 * lda;

    float acc[8][4];
#pragma unroll
    for (int i = 0; i < 8; i++)
#pragma unroll
        for (int j = 0; j < 4; j++) acc[i][j] = 0.f;

    for (int k0 = 0; k0 < K; k0 += BK) {
#pragma unroll
        for (int r = 0; r < 8; r++) {
            int idx = tid + 256 * r;
            int kk = idx & 15, m = idx >> 4;
            As[kk][m] = Abase[(size_t)m * lda + k0 + kk];
        }
        {
            int kk = tid >> 4;
            int c  = (tid & 15) * 4;
            float4 v = *reinterpret_cast<const float4*>(&W[(size_t)(k0 + kk) * N + n0 + c]);
            Ws[kk][c] = v.x; Ws[kk][c + 1] = v.y; Ws[kk][c + 2] = v.z; Ws[kk][c + 3] = v.w;
        }
        __syncthreads();
#pragma unroll
        for (int kk = 0; kk < BK; kk++) {
            float ra[8], rw[4];
#pragma unroll
            for (int i = 0; i < 8; i++) ra[i] = As[kk][ty + 16 * i];
#pragma unroll
            for (int j = 0; j < 4; j++) rw[j] = Ws[kk][tx + 16 * j];
#pragma unroll
            for (int i = 0; i < 8; i++)
#pragma unroll
                for (int j = 0; j < 4; j++) acc[i][j] = fmaf(ra[i], rw[j], acc[i][j]);
        }
        __syncthreads();
    }
#pragma unroll
    for (int i = 0; i < 8; i++) {
        int t = t0 + ty + 16 * i;
#pragma unroll
        for (int j = 0; j < 4; j++) epi(t, n0 + tx + 16 * j, acc[i][j]);
    }
}

// ------------------------- conversions -------------------------------------
__global__ __launch_bounds__(256) void nchw_to_bf(
    const float* __restrict__ in, __nv_bfloat16* __restrict__ out)
{
    __shared__ float sm[32][257];
    int tid = threadIdx.x;
    int t0 = blockIdx.x * 32;
    int bt = t0 >> 12, l0 = t0 & (TOK_L - 1);
    const float* src = in + (size_t)bt * CDIM * TOK_L + l0;
#pragma unroll 4
    for (int r = 0; r < 32; r++) {
        int idx = tid + 256 * r;
        int c = idx >> 5, l = idx & 31;
        sm[l][c] = src[(size_t)c * TOK_L + l];
    }
    __syncthreads();
#pragma unroll 4
    for (int r = 0; r < 32; r++) {
        int idx = tid + 256 * r;
        int c = idx & 255, l = idx >> 8;
        out[(size_t)(t0 + l) * CDIM + c] = __float2bfloat16(sm[l][c]);
    }
}

__global__ void f2bf(const float* __restrict__ in, __nv_bfloat16* __restrict__ out, int n)
{
    int i = blockIdx.x * 256 + threadIdx.x;
    if (i < n) out[i] = __float2bfloat16(in[i]);
}

// ------------------------- depthwise causal conv (K=4) + SiLU --------------
__global__ __launch_bounds__(256) void conv_silu_k(
    const float* __restrict__ w, const float* __restrict__ bias)
{
    int t = blockIdx.x;
    int d = blockIdx.y * 256 + threadIdx.x;
    int l = t & (TOK_L - 1);
    float acc = bias[d];
#pragma unroll
    for (int k = 0; k < 4; k++) {
        int li = l - 3 + k;
        if (li >= 0) acc = fmaf(g_xm[(size_t)(t - 3 + k) * DI + d], w[d * 4 + k], acc);
    }
    g_u[(size_t)t * DI + d] = acc * sigmoidf_(acc);
}

// ------------------------- chunked selective scan ---------------------------
__global__ __launch_bounds__(256) void scan_pass1(const float* __restrict__ A_log)
{
    int tid  = threadIdx.x;
    int g    = blockIdx.x * 16 + (tid >> 4);
    int lane = tid & 15;
    int d = g & (DI - 1);
    int c = (g >> 9) & (NCHUNK - 1);
    int b = g >> 14;

    float a = -__expf(A_log[d * NSTATE + lane]);
    float h = 0.f, p = 1.f;
    size_t base = (size_t)b * TOK_L + (size_t)c * CHUNK;
    for (int l = 0; l < CHUNK; l++) {
        size_t tt = base + l;
        float dtv = g_dt[tt * DI + d];
        float uv  = g_u [tt * DI + d];
        float Bv  = g_xdbl[tt * 64 + RRANK + lane];
        float dA  = __expf(dtv * a);
        h = fmaf(h, dA, (dtv * uv) * Bv);
        p *= dA;
    }
    size_t idx = (((size_t)b * NCHUNK + c) * DI + d) * NSTATE + lane;
    g_hend[idx] = h;
    g_Pend[idx] = p;
}

__global__ __launch_bounds__(256) void scan_pass2()
{
    int tid = blockIdx.x * 256 + threadIdx.x;
    int b  = tid >> 13;
    int dn = tid & 8191;
    float h = 0.f;
    for (int c = 0; c < NCHUNK; c++) {
        size_t idx = ((size_t)(b * NCHUNK + c)) * 8192 + dn;
        g_hstart[idx] = h;
        h = g_hend[idx] + g_Pend[idx] * h;
    }
}

__global__ __launch_bounds__(256) void scan_pass3(
    const float* __restrict__ A_log, const float* __restrict__ Dp)
{
    int tid  = threadIdx.x;
    int g    = blockIdx.x * 16 + (tid >> 4);
    int lane = tid & 15;
    int d = g & (DI - 1);
    int c = (g >> 9) & (NCHUNK - 1);
    int b = g >> 14;

    float a  = -__expf(A_log[d * NSTATE + lane]);
    float Dv = Dp[d];
    size_t sidx = (((size_t)b * NCHUNK + c) * DI + d) * NSTATE + lane;
    float h = g_hstart[sidx];
    size_t base = (size_t)b * TOK_L + (size_t)c * CHUNK;

    for (int l = 0; l < CHUNK; l++) {
        size_t tt = base + l;
        float dtv = g_dt[tt * DI + d];
        float uv  = g_u [tt * DI + d];
        float Bv  = g_xdbl[tt * 64 + RRANK + lane];
        float Cv  = g_xdbl[tt * 64 + RRANK + NSTATE + lane];
        float dA  = __expf(dtv * a);
        h = fmaf(h, dA, (dtv * uv) * Bv);
        float s = h * Cv;
        s += __shfl_xor_sync(0xffffffffu, s, 1);
        s += __shfl_xor_sync(0xffffffffu, s, 2);
        s += __shfl_xor_sync(0xffffffffu, s, 4);
        s += __shfl_xor_sync(0xffffffffu, s, 8);
        if (lane == 0) {
            float zv = g_z[tt * DI + d];
            g_ybf[tt * DI + d] = __float2bfloat16((s + uv * Dv) * (zv * sigmoidf_(zv)));
        }
    }
}

// ------------------------- LayerNorm + NCHW output -------------------------
__global__ __launch_bounds__(256) void ln_k(
    const float* __restrict__ g, const float* __restrict__ be,
    float* __restrict__ out)
{
    __shared__ float sm[32][257];
    int tid = threadIdx.x;
    int warp = tid >> 5, lane = tid & 31;
    int t0 = blockIdx.x * 32;

    for (int i = 0; i < 4; i++) {
        int tl = warp * 4 + i;
        int t  = t0 + tl;
        const float* row = g_res + (size_t)t * CDIM;
        float v[8];
        float s = 0.f, sq = 0.f;
#pragma unroll
        for (int r = 0; r < 2; r++) {
            float4 p = reinterpret_cast<const float4*>(row)[lane * 2 + r];
            v[r * 4] = p.x; v[r * 4 + 1] = p.y; v[r * 4 + 2] = p.z; v[r * 4 + 3] = p.w;
        }
#pragma unroll
        for (int k = 0; k < 8; k++) { s += v[k]; sq += v[k] * v[k]; }
#pragma unroll
        for (int o = 16; o; o >>= 1) {
            s  += __shfl_xor_sync(0xffffffffu, s,  o);
            sq += __shfl_xor_sync(0xffffffffu, sq, o);
        }
        float mu  = s * (1.f / CDIM);
        float var = sq * (1.f / CDIM) - mu * mu;
        float inv = rsqrtf(var + 1e-5f);
#pragma unroll
        for (int k = 0; k < 8; k++) {
            int c = lane * 8 + k;
            sm[tl][c] = (v[k] - mu) * inv * g[c] + be[c];
        }
    }
    __syncthreads();

    int bt = t0 >> 12;
    int l0 = t0 & (TOK_L - 1);
#pragma unroll 4
    for (int r = 0; r < 32; r++) {
        int idx = tid + 256 * r;
        int l = idx & 31;
        int c = idx >> 5;
        out[((size_t)bt * CDIM + c) * TOK_L + l0 + l] = sm[l][c];
    }
}

// ------------------------- launch ------------------------------------------
extern "C" void kernel_launch(void* const* d_in, const int* in_sizes, int n_in,
                              void* d_out, int out_size)
{
    const float* decoder  = (const float*)d_in[0];
    const float* encoder  = (const float*)d_in[1];
    const float* dec_w    = (const float*)d_in[2];
    const float* dec_b    = (const float*)d_in[3];
    const float* enc_w    = (const float*)d_in[4];
    const float* enc_b    = (const float*)d_in[5];
    const float* out_w    = (const float*)d_in[6];
    const float* out_b    = (const float*)d_in[7];
    const float* ln_g     = (const float*)d_in[8];
    const float* ln_b     = (const float*)d_in[9];
    const float* in_w     = (const float*)d_in[10];
    const float* in_b     = (const float*)d_in[11];
    const float* conv_w   = (const float*)d_in[12];
    const float* conv_b   = (const float*)d_in[13];
    const float* x_proj_w = (const float*)d_in[14];
    const float* dt_w     = (const float*)d_in[15];
    const float* dt_b     = (const float*)d_in[16];
    const float* A_log    = (const float*)d_in[17];
    const float* D_param  = (const float*)d_in[18];
    const float* m_out_w  = (const float*)d_in[19];
    const float* m_out_b  = (const float*)d_in[20];
    float* out = (float*)d_out;

    const int SMEM_GEMM = 3 * (128 * 128 + 64 * 256);   // 98304 bytes
    static int attr_done = 0;
    if (!attr_done) {
        cudaFuncSetAttribute(gemm_bf<EpiEnc >, cudaFuncAttributeMaxDynamicSharedMemorySize, SMEM_GEMM);
        cudaFuncSetAttribute(gemm_bf<EpiDec >, cudaFuncAttributeMaxDynamicSharedMemorySize, SMEM_GEMM);
        cudaFuncSetAttribute(gemm_bf<EpiXZ  >, cudaFuncAttributeMaxDynamicSharedMemorySize, SMEM_GEMM);
        cudaFuncSetAttribute(gemm_bf<EpiMout>, cudaFuncAttributeMaxDynamicSharedMemorySize, SMEM_GEMM);
        cudaFuncSetAttribute(gemm_bf<EpiOut >, cudaFuncAttributeMaxDynamicSharedMemorySize, SMEM_GEMM);
        attr_done = 1;
    }

    dim3 blk(256);
    const int MB = NTOK / 128;   // 64 M-tiles

    // bf16 weight + activation conversion
    __nv_bfloat16 *wdec, *wenc, *win, *wmout, *wout, *decbf, *encbf;
    cudaGetSymbolAddress((void**)&wdec,  g_wdec);
    cudaGetSymbolAddress((void**)&wenc,  g_wenc);
    cudaGetSymbolAddress((void**)&win,   g_win);
    cudaGetSymbolAddress((void**)&wmout, g_wmout);
    cudaGetSymbolAddress((void**)&wout,  g_wout);
    cudaGetSymbolAddress((void**)&decbf, g_decbf);
    cudaGetSymbolAddress((void**)&encbf, g_encbf);
    __nv_bfloat16 *combbf, *ybf, *gatedbf;
    cudaGetSymbolAddress((void**)&combbf,  g_combbf);
    cudaGetSymbolAddress((void**)&ybf,     g_ybf);
    cudaGetSymbolAddress((void**)&gatedbf, g_gatedbf);

    f2bf<<<(CDIM * 2 * DI + 255) / 256, blk>>>(dec_w,   wdec,  CDIM * 2 * DI);
    f2bf<<<(CDIM * DI + 255) / 256, blk>>>(enc_w,       wenc,  CDIM * DI);
    f2bf<<<(DI * 2 * DI + 255) / 256, blk>>>(in_w,      win,   DI * 2 * DI);
    f2bf<<<(DI * DI + 255) / 256, blk>>>(m_out_w,       wmout, DI * DI);
    f2bf<<<(DI * CDIM + 255) / 256, blk>>>(out_w,       wout,  DI * CDIM);
    nchw_to_bf<<<NTOK / 32, blk>>>(decoder, decbf);
    nchw_to_bf<<<NTOK / 32, blk>>>(encoder, encbf);

    // 1. enc_p = enc @ enc_w + enc_b               (K=256, N=512)
    gemm_bf<EpiEnc ><<<dim3(DI / 128, MB), blk, SMEM_GEMM>>>(encbf, wenc, CDIM, DI, CDIM, EpiEnc{enc_b});
    // 2. dec_proj -> combined(bf16) + gate          (K=256, N=1024)
    gemm_bf<EpiDec ><<<dim3(2 * DI / 128, MB), blk, SMEM_GEMM>>>(decbf, wdec, CDIM, 2 * DI, CDIM, EpiDec{dec_b});
    // 3. xz = combined @ in_w -> xm, z              (K=512, N=1024)
    gemm_bf<EpiXZ  ><<<dim3(2 * DI / 128, MB), blk, SMEM_GEMM>>>(combbf, win, DI, 2 * DI, DI, EpiXZ{in_b});
    // 4. depthwise conv + SiLU -> u
    conv_silu_k<<<dim3(NTOK, DI / 256), blk>>>(conv_w, conv_b);
    // 5. x_dbl = u @ x_proj_w                      (K=512, N=64)
    gemm_small<EpiXdbl><<<dim3(1, MB), blk>>>(g_u, x_proj_w, DI, 64, DI, EpiXdbl{});
    // 6. dt = softplus(x_dbl[:, :32] @ dt_w + dt_b) (K=32, N=512, lda=64)
    gemm_small<EpiDt  ><<<dim3(DI / 64, MB), blk>>>(g_xdbl, dt_w, RRANK, DI, 64, EpiDt{dt_b});
    // 7-9. chunked selective scan (pass3 writes y bf16)
    scan_pass1<<<NBATCH * NCHUNK * DI / 16, blk>>>(A_log);
    scan_pass2<<<NBATCH * DI * NSTATE / 256, blk>>>();
    scan_pass3<<<NBATCH * NCHUNK * DI / 16, blk>>>(A_log, D_param);
    // 10. processed = y @ m_out_w + b, * sigmoid(gate)  (K=512, N=512)
    gemm_bf<EpiMout><<<dim3(DI / 128, MB), blk, SMEM_GEMM>>>(ybf, wmout, DI, DI, DI, EpiMout{m_out_b});
    // 11. out = gated @ out_w + out_b + dec        (K=512, N=256)
    gemm_bf<EpiOut ><<<dim3(CDIM / 128, MB), blk, SMEM_GEMM>>>(gatedbf, wout, DI, CDIM, DI, EpiOut{out_b, decoder});
    // 12. LayerNorm + transpose to NCHW
    ln_k<<<NTOK / 32, blk>>>(ln_g, ln_b, out);
}

// round 4
// speedup vs baseline: 10.7878x; 1.3320x over previous
#include <cuda_runtime.h>
#include <cuda_bf16.h>
#include <math.h>
#include <stdint.h>

// Problem constants
#define TOK_L   4096
#define NBATCH  2
#define NTOK    8192
#define CDIM    256
#define DI      512
#define NSTATE  16
#define RRANK   32
#define CHUNK   128
#define NCHUNK  32
#define NFUSED  640          // 512 (dt) + 32 (B,C) + 96 pad

// ------------------------- scratch (device globals) -------------------------
__device__ float g_res  [NTOK * CDIM];
__device__ float g_hend  [NBATCH * NCHUNK * DI * NSTATE];
__device__ float g_Pend  [NBATCH * NCHUNK * DI * NSTATE];
__device__ float g_hstart[NBATCH * NCHUNK * DI * NSTATE];

// bf16 activations
__device__ __nv_bfloat16 g_decbf  [NTOK * CDIM];
__device__ __nv_bfloat16 g_encbf  [NTOK * CDIM];
__device__ __nv_bfloat16 g_encp   [NTOK * DI];
__device__ __nv_bfloat16 g_gate   [NTOK * DI];
__device__ __nv_bfloat16 g_combbf [NTOK * DI];
__device__ __nv_bfloat16 g_xm     [NTOK * DI];
__device__ __nv_bfloat16 g_z      [NTOK * DI];
__device__ __nv_bfloat16 g_u      [NTOK * DI];
__device__ __nv_bfloat16 g_dt     [NTOK * DI];
__device__ __nv_bfloat16 g_bc     [NTOK * 32];
__device__ __nv_bfloat16 g_ybf    [NTOK * DI];
__device__ __nv_bfloat16 g_gatedbf[NTOK * DI];
// bf16 weights
__device__ __nv_bfloat16 g_wdec  [CDIM * 2 * DI];
__device__ __nv_bfloat16 g_wenc  [CDIM * DI];
__device__ __nv_bfloat16 g_win   [DI * 2 * DI];
__device__ __nv_bfloat16 g_wmout [DI * DI];
__device__ __nv_bfloat16 g_wout  [DI * CDIM];
__device__ __nv_bfloat16 g_wfused[DI * NFUSED];

// ------------------------- helpers -----------------------------------------
__device__ __forceinline__ float sigmoidf_(float x) { return 1.f / (1.f + __expf(-x)); }

#define CP_ASYNC16(dst, src) \
    asm volatile("cp.async.cg.shared.global [%0], [%1], 16;\n" :: "r"(dst), "l"(src))
#define CP_COMMIT() asm volatile("cp.async.commit_group;\n" ::: "memory")
#define CP_WAIT1()  asm volatile("cp.async.wait_group 1;\n" ::: "memory")

#define LDSM_X4(r0,r1,r2,r3,addr) \
    asm volatile("ldmatrix.sync.aligned.m8n8.x4.shared.b16 {%0,%1,%2,%3}, [%4];" \
        : "=r"(r0),"=r"(r1),"=r"(r2),"=r"(r3) : "r"(addr))
#define LDSM_X4T(r0,r1,r2,r3,addr) \
    asm volatile("ldmatrix.sync.aligned.m8n8.x4.trans.shared.b16 {%0,%1,%2,%3}, [%4];" \
        : "=r"(r0),"=r"(r1),"=r"(r2),"=r"(r3) : "r"(addr))

#define MMA16816(d, a, b) \
    asm volatile("mma.sync.aligned.m16n8k16.row.col.f32.bf16.bf16.f32 " \
        "{%0,%1,%2,%3}, {%4,%5,%6,%7}, {%8,%9}, {%0,%1,%2,%3};" \
        : "+f"(d[0]),"+f"(d[1]),"+f"(d[2]),"+f"(d[3]) \
        : "r"(a[0]),"r"(a[1]),"r"(a[2]),"r"(a[3]), "r"(b[0]),"r"(b[1]))

// ------------------------- epilogue functors -------------------------------
struct EpiEnc {
    const float* b;
    __device__ void operator()(int t, int j, float a) const {
        g_encp[(size_t)t * DI + j] = __float2bfloat16(a + b[j]);
    }
};
struct EpiDec {
    const float* b;
    __device__ void operator()(int t, int j, float a) const {
        float v = a + b[j];
        if (j < DI) {
            float e = __bfloat162float(g_encp[(size_t)t * DI + j]);
            g_combbf[(size_t)t * DI + j] = __float2bfloat16(v * sigmoidf_(e) + e);
        } else {
            g_gate[(size_t)t * DI + (j - DI)] = __float2bfloat16(v);
        }
    }
};
struct EpiXZ {
    const float* b;
    __device__ void operator()(int t, int j, float a) const {
        float v = a + b[j];
        if (j < DI) g_xm[(size_t)t * DI + j] = __float2bfloat16(v);
        else        g_z [(size_t)t * DI + (j - DI)] = __float2bfloat16(v);
    }
};
struct EpiFused {   // dt = softplus(u @ Wcomb + dt_b); B,C = u @ xproj[:,32:64]
    const float* dtb;
    __device__ void operator()(int t, int j, float a) const {
        if (j < DI) {
            float x = a + dtb[j];
            float sp = (x > 20.f) ? x : log1pf(expf(x));
            g_dt[(size_t)t * DI + j] = __float2bfloat16(sp);
        } else if (j < DI + 32) {
            g_bc[(size_t)t * 32 + (j - DI)] = __float2bfloat16(a);
        }
    }
};
struct EpiMout {
    const float* b;
    __device__ void operator()(int t, int j, float a) const {
        float v = a + b[j];
        float g = __bfloat162float(g_gate[(size_t)t * DI + j]);
        g_gatedbf[(size_t)t * DI + j] = __float2bfloat16(v * sigmoidf_(g));
    }
};
struct EpiOut {
    const float* b; const float* dec;
    __device__ void operator()(int t, int j, float a) const {
        int bt = t >> 12, l = t & (TOK_L - 1);
        float d = dec[((size_t)bt * CDIM + j) * TOK_L + l];
        g_res[(size_t)t * CDIM + j] = a + b[j] + d;
    }
};

// ------------------------- bf16 tensor-core GEMM ---------------------------
template <class Epi>
__global__ __launch_bounds__(256) void gemm_bf(
    const __nv_bfloat16* __restrict__ A, const __nv_bfloat16* __restrict__ W,
    int K, int N, int lda, Epi epi)
{
    extern __shared__ char smem[];
    const int ASZ = 128 * 128;
    const int BSZ = 64 * 256;
    uint32_t sbase = (uint32_t)__cvta_generic_to_shared(smem);

    int tid = threadIdx.x;
    int w = tid >> 5, lane = tid & 31;
    int wm = w >> 2, wn = w & 3;
    int t0 = blockIdx.y * 128, n0 = blockIdx.x * 128;

    const __nv_bfloat16* Ab = A + (size_t)t0 * lda;
    const __nv_bfloat16* Wb = W + n0;

    auto loadStage = [&](int s, int k0) {
        uint32_t as = sbase + s * (ASZ + BSZ);
        uint32_t bs = as + ASZ;
#pragma unroll
        for (int r = 0; r < 4; r++) {
            int idx = tid + 256 * r;
            int m = idx >> 3, kb = idx & 7;
            uint32_t off = m * 128 + ((kb ^ (m & 7)) << 4);
            CP_ASYNC16(as + off, Ab + (size_t)m * lda + k0 + kb * 8);
        }
#pragma unroll
        for (int r = 0; r < 4; r++) {
            int idx = tid + 256 * r;
            int k = idx >> 4, nb = idx & 15;
            uint32_t off = k * 256 + ((nb >> 3) << 7) + (((nb & 7) ^ (k & 7)) << 4);
            CP_ASYNC16(bs + off, Wb + (size_t)(k0 + k) * N + nb * 8);
        }
    };

    float acc[4][4][4];
#pragma unroll
    for (int i = 0; i < 4; i++)
#pragma unroll
        for (int j = 0; j < 4; j++)
#pragma unroll
            for (int c = 0; c < 4; c++) acc[i][j][c] = 0.f;

    int nk = K / 64;
    loadStage(0, 0);
    CP_COMMIT();
    if (nk > 1) loadStage(1, 64);
    CP_COMMIT();

    for (int kt = 0; kt < nk; kt++) {
        CP_WAIT1();
        __syncthreads();
        int s = kt % 3;
        if (kt + 2 < nk) loadStage((kt + 2) % 3, (kt + 2) * 64);
        CP_COMMIT();

        uint32_t as = sbase + s * (ASZ + BSZ);
        uint32_t bs = as + ASZ;
        int sub = lane >> 3;
#pragma unroll
        for (int ks = 0; ks < 4; ks++) {
            uint32_t afr[4][4];
            uint32_t bfr[4][2];
#pragma unroll
            for (int i = 0; i < 4; i++) {
                int row = wm * 64 + i * 16 + (lane & 7) + ((sub & 1) << 3);
                int kb = ks * 2 + (sub >> 1);
                uint32_t addr = as + row * 128 + ((kb ^ (row & 7)) << 4);
                LDSM_X4(afr[i][0], afr[i][1], afr[i][2], afr[i][3], addr);
            }
#pragma unroll
            for (int p = 0; p < 2; p++) {
                int k = ks * 16 + (lane & 7) + ((sub & 1) << 3);
                int nb = wn * 4 + p * 2 + (sub >> 1);
                uint32_t addr = bs + k * 256 + ((nb >> 3) << 7) + (((nb & 7) ^ (k & 7)) << 4);
                uint32_t r0, r1, r2, r3;
                LDSM_X4T(r0, r1, r2, r3, addr);
                bfr[p * 2][0] = r0;     bfr[p * 2][1] = r1;
                bfr[p * 2 + 1][0] = r2; bfr[p * 2 + 1][1] = r3;
            }
#pragma unroll
            for (int i = 0; i < 4; i++)
#pragma unroll
                for (int j = 0; j < 4; j++) MMA16816(acc[i][j], afr[i], bfr[j]);
        }
        __syncthreads();
    }

    int rbase = t0 + wm * 64 + (lane >> 2);
    int cbase = n0 + wn * 32 + (lane & 3) * 2;
#pragma unroll
    for (int i = 0; i < 4; i++)
#pragma unroll
        for (int j = 0; j < 4; j++) {
            epi(rbase + i * 16,     cbase + j * 8,     acc[i][j][0]);
            epi(rbase + i * 16,     cbase + j * 8 + 1, acc[i][j][1]);
            epi(rbase + i * 16 + 8, cbase + j * 8,     acc[i][j][2]);
            epi(rbase + i * 16 + 8, cbase + j * 8 + 1, acc[i][j][3]);
        }
}

// ------------------------- weight prep kernels ------------------------------
// fused weight: [Wcomb(512) | xproj B,C cols 32..63 (32) | zero pad (96)]
__global__ __launch_bounds__(256) void wcomb_k(
    const float* __restrict__ xproj, const float* __restrict__ dtw)
{
    int idx = blockIdx.x * 256 + threadIdx.x;
    if (idx >= DI * NFUSED) return;
    int k = idx / NFUSED, j = idx % NFUSED;
    float v = 0.f;
    if (j < DI) {
#pragma unroll
        for (int r = 0; r < RRANK; r++)
            v = fmaf(xproj[k * 64 + r], dtw[r * DI + j], v);
    } else if (j < DI + 32) {
        v = xproj[k * 64 + 32 + (j - DI)];
    }
    g_wfused[idx] = __float2bfloat16(v);
}

#define SZ_WDEC (CDIM * 2 * DI)
#define SZ_WENC (CDIM * DI)
#define SZ_WIN  (DI * 2 * DI)
#define SZ_WMOUT (DI * DI)
#define SZ_WOUT (DI * CDIM)
#define SZ_ALL  (SZ_WDEC + SZ_WENC + SZ_WIN + SZ_WMOUT + SZ_WOUT)

__global__ __launch_bounds__(256) void f2bf_all(
    const float* __restrict__ dec_w, const float* __restrict__ enc_w,
    const float* __restrict__ in_w, const float* __restrict__ m_out_w,
    const float* __restrict__ out_w)
{
    int i = blockIdx.x * 256 + threadIdx.x;
    if (i < SZ_WDEC) { g_wdec[i] = __float2bfloat16(dec_w[i]); return; }
    i -= SZ_WDEC;
    if (i < SZ_WENC) { g_wenc[i] = __float2bfloat16(enc_w[i]); return; }
    i -= SZ_WENC;
    if (i < SZ_WIN)  { g_win[i] = __float2bfloat16(in_w[i]); return; }
    i -= SZ_WIN;
    if (i < SZ_WMOUT){ g_wmout[i] = __float2bfloat16(m_out_w[i]); return; }
    i -= SZ_WMOUT;
    if (i < SZ_WOUT) { g_wout[i] = __float2bfloat16(out_w[i]); }
}

// ------------------------- NCHW -> row-major bf16 (both inputs) ------------
__global__ __launch_bounds__(256) void nchw_to_bf2(
    const float* __restrict__ dec, const float* __restrict__ enc)
{
    __shared__ float sm[32][257];
    int tid = threadIdx.x;
    int nblk = gridDim.x >> 1;
    int which = blockIdx.x >= nblk;
    const float* in = which ? enc : dec;
    __nv_bfloat16* out = which ? g_encbf : g_decbf;
    int t0 = (blockIdx.x - which * nblk) * 32;
    int bt = t0 >> 12, l0 = t0 & (TOK_L - 1);
    const float* src = in + (size_t)bt * CDIM * TOK_L + l0;
#pragma unroll 4
    for (int r = 0; r < 32; r++) {
        int idx = tid + 256 * r;
        int c = idx >> 5, l = idx & 31;
        sm[l][c] = src[(size_t)c * TOK_L + l];
    }
    __syncthreads();
#pragma unroll 4
    for (int r = 0; r < 32; r++) {
        int idx = tid + 256 * r;
        int c = idx & 255, l = idx >> 8;
        out[(size_t)(t0 + l) * CDIM + c] = __float2bfloat16(sm[l][c]);
    }
}

// ------------------------- depthwise causal conv (K=4) + SiLU --------------
__global__ __launch_bounds__(256) void conv_silu_k(
    const float* __restrict__ w, const float* __restrict__ bias)
{
    int t = blockIdx.x;
    int d = blockIdx.y * 256 + threadIdx.x;
    int l = t & (TOK_L - 1);
    float acc = bias[d];
#pragma unroll
    for (int k = 0; k < 4; k++) {
        int li = l - 3 + k;
        if (li >= 0)
            acc = fmaf(__bfloat162float(g_xm[(size_t)(t - 3 + k) * DI + d]), w[d * 4 + k], acc);
    }
    g_u[(size_t)t * DI + d] = __float2bfloat16(acc * sigmoidf_(acc));
}

// ------------------------- chunked selective scan ---------------------------
__global__ __launch_bounds__(256) void scan_pass1(const float* __restrict__ A_log)
{
    int tid  = threadIdx.x;
    int g    = blockIdx.x * 16 + (tid >> 4);
    int lane = tid & 15;
    int d = g & (DI - 1);
    int c = (g >> 9) & (NCHUNK - 1);
    int b = g >> 14;

    float a = -__expf(A_log[d * NSTATE + lane]);
    float h = 0.f, p = 1.f;
    size_t base = (size_t)b * TOK_L + (size_t)c * CHUNK;
    for (int l = 0; l < CHUNK; l++) {
        size_t tt = base + l;
        float dtv = __bfloat162float(g_dt[tt * DI + d]);
        float uv  = __bfloat162float(g_u [tt * DI + d]);
        float Bv  = __bfloat162float(g_bc[tt * 32 + lane]);
        float dA  = __expf(dtv * a);
        h = fmaf(h, dA, (dtv * uv) * Bv);
        p *= dA;
    }
    size_t idx = (((size_t)b * NCHUNK + c) * DI + d) * NSTATE + lane;
    g_hend[idx] = h;
    g_Pend[idx] = p;
}

__global__ __launch_bounds__(256) void scan_pass2()
{
    int tid = blockIdx.x * 256 + threadIdx.x;
    int b  = tid >> 13;
    int dn = tid & 8191;
    float h = 0.f;
    for (int c = 0; c < NCHUNK; c++) {
        size_t idx = ((size_t)(b * NCHUNK + c)) * 8192 + dn;
        g_hstart[idx] = h;
        h = g_hend[idx] + g_Pend[idx] * h;
    }
}

__global__ __launch_bounds__(256) void scan_pass3(
    const float* __restrict__ A_log, const float* __restrict__ Dp)
{
    int tid  = threadIdx.x;
    int g    = blockIdx.x * 16 + (tid >> 4);
    int lane = tid & 15;
    int d = g & (DI - 1);
    int c = (g >> 9) & (NCHUNK - 1);
    int b = g >> 14;

    float a  = -__expf(A_log[d * NSTATE + lane]);
    float Dv = Dp[d];
    size_t sidx = (((size_t)b * NCHUNK + c) * DI + d) * NSTATE + lane;
    float h = g_hstart[sidx];
    size_t base = (size_t)b * TOK_L + (size_t)c * CHUNK;

    for (int l = 0; l < CHUNK; l++) {
        size_t tt = base + l;
        float dtv = __bfloat162float(g_dt[tt * DI + d]);
        float uv  = __bfloat162float(g_u [tt * DI + d]);
        float Bv  = __bfloat162float(g_bc[tt * 32 + lane]);
        float Cv  = __bfloat162float(g_bc[tt * 32 + 16 + lane]);
        float dA  = __expf(dtv * a);
        h = fmaf(h, dA, (dtv * uv) * Bv);
        float s = h * Cv;
        s += __shfl_xor_sync(0xffffffffu, s, 1);
        s += __shfl_xor_sync(0xffffffffu, s, 2);
        s += __shfl_xor_sync(0xffffffffu, s, 4);
        s += __shfl_xor_sync(0xffffffffu, s, 8);
        if (lane == 0) {
            float zv = __bfloat162float(g_z[tt * DI + d]);
            g_ybf[tt * DI + d] = __float2bfloat16((s + uv * Dv) * (zv * sigmoidf_(zv)));
        }
    }
}

// ------------------------- LayerNorm + NCHW output -------------------------
__global__ __launch_bounds__(256) void ln_k(
    const float* __restrict__ g, const float* __restrict__ be,
    float* __restrict__ out)
{
    __shared__ float sm[32][257];
    int tid = threadIdx.x;
    int warp = tid >> 5, lane = tid & 31;
    int t0 = blockIdx.x * 32;

    for (int i = 0; i < 4; i++) {
        int tl = warp * 4 + i;
        int t  = t0 + tl;
        const float* row = g_res + (size_t)t * CDIM;
        float v[8];
        float s = 0.f, sq = 0.f;
#pragma unroll
        for (int r = 0; r < 2; r++) {
            float4 p = reinterpret_cast<const float4*>(row)[lane * 2 + r];
            v[r * 4] = p.x; v[r * 4 + 1] = p.y; v[r * 4 + 2] = p.z; v[r * 4 + 3] = p.w;
        }
#pragma unroll
        for (int k = 0; k < 8; k++) { s += v[k]; sq += v[k] * v[k]; }
#pragma unroll
        for (int o = 16; o; o >>= 1) {
            s  += __shfl_xor_sync(0xffffffffu, s,  o);
            sq += __shfl_xor_sync(0xffffffffu, sq, o);
        }
        float mu  = s * (1.f / CDIM);
        float var = sq * (1.f / CDIM) - mu * mu;
        float inv = rsqrtf(var + 1e-5f);
#pragma unroll
        for (int k = 0; k < 8; k++) {
            int c = lane * 8 + k;
            sm[tl][c] = (v[k] - mu) * inv * g[c] + be[c];
        }
    }
    __syncthreads();

    int bt = t0 >> 12;
    int l0 = t0 & (TOK_L - 1);
#pragma unroll 4
    for (int r = 0; r < 32; r++) {
        int idx = tid + 256 * r;
        int l = idx & 31;
        int c = idx >> 5;
        out[((size_t)bt * CDIM + c) * TOK_L + l0 + l] = sm[l][c];
    }
}

// ------------------------- launch ------------------------------------------
extern "C" void kernel_launch(void* const* d_in, const int* in_sizes, int n_in,
                              void* d_out, int out_size)
{
    const float* decoder  = (const float*)d_in[0];
    const float* encoder  = (const float*)d_in[1];
    const float* dec_w    = (const float*)d_in[2];
    const float* dec_b    = (const float*)d_in[3];
    const float* enc_w    = (const float*)d_in[4];
    const float* enc_b    = (const float*)d_in[5];
    const float* out_w    = (const float*)d_in[6];
    const float* out_b    = (const float*)d_in[7];
    const float* ln_g     = (const float*)d_in[8];
    const float* ln_b     = (const float*)d_in[9];
    const float* in_w     = (const float*)d_in[10];
    const float* in_b     = (const float*)d_in[11];
    const float* conv_w   = (const float*)d_in[12];
    const float* conv_b   = (const float*)d_in[13];
    const float* x_proj_w = (const float*)d_in[14];
    const float* dt_w     = (const float*)d_in[15];
    const float* dt_b     = (const float*)d_in[16];
    const float* A_log    = (const float*)d_in[17];
    const float* D_param  = (const float*)d_in[18];
    const float* m_out_w  = (const float*)d_in[19];
    const float* m_out_b  = (const float*)d_in[20];
    float* out = (float*)d_out;

    const int SMEM_GEMM = 3 * (128 * 128 + 64 * 256);
    static int attr_done = 0;
    if (!attr_done) {
        cudaFuncSetAttribute(gemm_bf<EpiEnc  >, cudaFuncAttributeMaxDynamicSharedMemorySize, SMEM_GEMM);
        cudaFuncSetAttribute(gemm_bf<EpiDec  >, cudaFuncAttributeMaxDynamicSharedMemorySize, SMEM_GEMM);
        cudaFuncSetAttribute(gemm_bf<EpiXZ   >, cudaFuncAttributeMaxDynamicSharedMemorySize, SMEM_GEMM);
        cudaFuncSetAttribute(gemm_bf<EpiFused>, cudaFuncAttributeMaxDynamicSharedMemorySize, SMEM_GEMM);
        cudaFuncSetAttribute(gemm_bf<EpiMout >, cudaFuncAttributeMaxDynamicSharedMemorySize, SMEM_GEMM);
        cudaFuncSetAttribute(gemm_bf<EpiOut  >, cudaFuncAttributeMaxDynamicSharedMemorySize, SMEM_GEMM);
        attr_done = 1;
    }

    dim3 blk(256);
    const int MB = NTOK / 128;   // 64 M-tiles

    __nv_bfloat16 *wdec, *wenc, *win, *wmout, *wout, *wfused;
    __nv_bfloat16 *decbf, *encbf, *combbf, *ubf, *ybf, *gatedbf;
    cudaGetSymbolAddress((void**)&wdec,   g_wdec);
    cudaGetSymbolAddress((void**)&wenc,   g_wenc);
    cudaGetSymbolAddress((void**)&win,    g_win);
    cudaGetSymbolAddress((void**)&wmout,  g_wmout);
    cudaGetSymbolAddress((void**)&wout,   g_wout);
    cudaGetSymbolAddress((void**)&wfused, g_wfused);
    cudaGetSymbolAddress((void**)&decbf,  g_decbf);
    cudaGetSymbolAddress((void**)&encbf,  g_encbf);
    cudaGetSymbolAddress((void**)&combbf, g_combbf);
    cudaGetSymbolAddress((void**)&ubf,    g_u);
    cudaGetSymbolAddress((void**)&ybf,    g_ybf);
    cudaGetSymbolAddress((void**)&gatedbf,g_gatedbf);

    // weight prep (2 launches)
    f2bf_all<<<(SZ_ALL + 255) / 256, blk>>>(dec_w, enc_w, in_w, m_out_w, out_w);
    wcomb_k<<<(DI * NFUSED + 255) / 256, blk>>>(x_proj_w, dt_w);
    // input transpose+convert (1 launch, both tensors)
    nchw_to_bf2<<<2 * (NTOK / 32), blk>>>(decoder, encoder);

    // 1. enc_p = enc @ enc_w + enc_b               (K=256, N=512)
    gemm_bf<EpiEnc  ><<<dim3(DI / 128, MB), blk, SMEM_GEMM>>>(encbf, wenc, CDIM, DI, CDIM, EpiEnc{enc_b});
    // 2. dec_proj -> combined(bf16) + gate          (K=256, N=1024)
    gemm_bf<EpiDec  ><<<dim3(2 * DI / 128, MB), blk, SMEM_GEMM>>>(decbf, wdec, CDIM, 2 * DI, CDIM, EpiDec{dec_b});
    // 3. xz = combined @ in_w -> xm, z              (K=512, N=1024)
    gemm_bf<EpiXZ   ><<<dim3(2 * DI / 128, MB), blk, SMEM_GEMM>>>(combbf, win, DI, 2 * DI, DI, EpiXZ{in_b});
    // 4. depthwise conv + SiLU -> u (bf16)
    conv_silu_k<<<dim3(NTOK, DI / 256), blk>>>(conv_w, conv_b);
    // 5. fused: dt = softplus(u@Wcomb + dt_b), B/C = u@xproj_BC   (K=512, N=640)
    gemm_bf<EpiFused><<<dim3(NFUSED / 128, MB), blk, SMEM_GEMM>>>(ubf, wfused, DI, NFUSED, DI, EpiFused{dt_b});
    // 6-8. chunked selective scan
    scan_pass1<<<NBATCH * NCHUNK * DI / 16, blk>>>(A_log);
    scan_pass2<<<NBATCH * DI * NSTATE / 256, blk>>>();
    scan_pass3<<<NBATCH * NCHUNK * DI / 16, blk>>>(A_log, D_param);
    // 9. processed = y @ m_out_w + b, * sigmoid(gate)  (K=512, N=512)
    gemm_bf<EpiMout ><<<dim3(DI / 128, MB), blk, SMEM_GEMM>>>(ybf, wmout, DI, DI, DI, EpiMout{m_out_b});
    // 10. out = gated @ out_w + out_b + dec        (K=512, N=256)
    gemm_bf<EpiOut  ><<<dim3(CDIM / 128, MB), blk, SMEM_GEMM>>>(gatedbf, wout, DI, CDIM, DI, EpiOut{out_b, decoder});
    // 11. LayerNorm + transpose to NCHW
    ln_k<<<NTOK / 32, blk>>>(ln_g, ln_b, out);
}